// round 5
// baseline (speedup 1.0000x reference)
#include <cuda_runtime.h>
#include <stdint.h>

// -----------------------------------------------------------------------------
// Polynomial edge-energy + segment sum. (indices are INT32 — jax x64 disabled)
//   per edge e: x = |pos[m0]-pos[m1]|, V = v0[t0,t1] + sum_p ks[p,t0,t1]*x^(p+1)
//   y[g] = segment sum over sorted mapping_batch
// -----------------------------------------------------------------------------

#define MAX_NODES (1 << 17)   // 131072 >= N=100000
#define MAX_TT    1024        // >= T*T = 625
#define MAX_G     1024        // >= n_graphs = 512

__device__ float4 g_nodes[MAX_NODES];   // xyz + type-as-float: one 16B gather/endpoint

// ---- prep: pack (pos, atom_type) into one float4 per node -------------------
__global__ void pack_nodes_kernel(const float* __restrict__ pos,
                                  const int* __restrict__ types,
                                  int N) {
    int i = blockIdx.x * blockDim.x + threadIdx.x;
    if (i < N) {
        float4 v;
        v.x = pos[3 * i + 0];
        v.y = pos[3 * i + 1];
        v.z = pos[3 * i + 2];
        v.w = (float)types[i];
        g_nodes[i] = v;
    }
}

// ---- per-edge energy ---------------------------------------------------------
__device__ __forceinline__ float edge_V(int i0, int i1,
                                        const float4* __restrict__ s_kk,
                                        const float* __restrict__ s_v0,
                                        int T) {
    float4 n0 = g_nodes[i0];
    float4 n1 = g_nodes[i1];
    float dx = n0.x - n1.x;
    float dy = n0.y - n1.y;
    float dz = n0.z - n1.z;
    float x2 = fmaf(dx, dx, fmaf(dy, dy, dz * dz));
    float x  = sqrtf(x2);
    int idx = (int)n0.w * T + (int)n1.w;
    float4 k = s_kk[idx];
    float  v = s_v0[idx];
    // v0 + x*(k1 + x*(k2 + x*(k3 + x*k4)))
    return fmaf(x, fmaf(x, fmaf(x, fmaf(x, k.w, k.z), k.y), k.x), v);
}

// ---- main kernel -------------------------------------------------------------
__global__ void __launch_bounds__(256)
poly_main_kernel(const int* __restrict__ map0,
                 const int* __restrict__ map1,
                 const int* __restrict__ batch,
                 const float* __restrict__ ks,
                 const float* __restrict__ v0g,
                 float* __restrict__ y,
                 long long C,        // number of 4-edge chunks
                 long long E,        // total edges (tail handled separately)
                 int T, int degs, int G) {
    __shared__ float4 s_kk[MAX_TT];
    __shared__ float  s_v0[MAX_TT];
    __shared__ float  s_y[MAX_G];

    const int TT = T * T;
    for (int i = threadIdx.x; i < TT; i += blockDim.x) {
        float4 k;
        k.x = ks[i];
        k.y = (degs > 1) ? ks[TT + i]     : 0.f;
        k.z = (degs > 2) ? ks[2 * TT + i] : 0.f;
        k.w = (degs > 3) ? ks[3 * TT + i] : 0.f;
        s_kk[i] = k;
        s_v0[i] = v0g[i];
    }
    for (int i = threadIdx.x; i < G; i += blockDim.x) s_y[i] = 0.f;
    __syncthreads();

    // contiguous chunk range per block -> block sees only 1-2 segments
    long long cpb    = (C + gridDim.x - 1) / gridDim.x;
    long long cstart = (long long)blockIdx.x * cpb;
    long long cend   = cstart + cpb;
    if (cend > C) cend = C;

    if (cstart < cend) {
        const int4* __restrict__ m0v = (const int4*)map0;
        const int4* __restrict__ m1v = (const int4*)map1;
        const int4* __restrict__ bv  = (const int4*)batch;
        long long range = cend - cstart;
        int iters = (int)((range + blockDim.x - 1) / blockDim.x);
        int lane  = threadIdx.x & 31;

        for (int it = 0; it < iters; ++it) {
            long long c = cstart + (long long)it * blockDim.x + threadIdx.x;
            bool valid = (c < cend);
            float V0 = 0.f, V1 = 0.f, V2 = 0.f, V3 = 0.f;
            int4 bb = make_int4(0, 0, 0, 0);
            if (valid) {
                int4 ma = m0v[c];
                int4 mb = m1v[c];
                bb = bv[c];
                V0 = edge_V(ma.x, mb.x, s_kk, s_v0, T);
                V1 = edge_V(ma.y, mb.y, s_kk, s_v0, T);
                V2 = edge_V(ma.z, mb.z, s_kk, s_v0, T);
                V3 = edge_V(ma.w, mb.w, s_kk, s_v0, T);
            }
            // warp-uniform segment fast path (batches sorted -> ~always taken)
            int bl = __shfl_sync(0xffffffffu, bb.x, 0);
            bool uni = valid && (bb.x == bl) && (bb.y == bl) &&
                                (bb.z == bl) && (bb.w == bl);
            if (__ballot_sync(0xffffffffu, uni) == 0xffffffffu) {
                float s = (V0 + V1) + (V2 + V3);
                #pragma unroll
                for (int o = 16; o > 0; o >>= 1)
                    s += __shfl_xor_sync(0xffffffffu, s, o);
                if (lane == 0) atomicAdd(&s_y[bl], s);
            } else if (valid) {
                atomicAdd(&s_y[bb.x], V0);
                atomicAdd(&s_y[bb.y], V1);
                atomicAdd(&s_y[bb.z], V2);
                atomicAdd(&s_y[bb.w], V3);
            }
        }
    }

    // trailing edges (E not divisible by 4)
    if (blockIdx.x == 0 && threadIdx.x == 0) {
        for (long long e = C * 4; e < E; ++e) {
            float V = edge_V(map0[e], map1[e], s_kk, s_v0, T);
            atomicAdd(&s_y[batch[e]], V);
        }
    }

    __syncthreads();
    for (int i = threadIdx.x; i < G; i += blockDim.x) {
        float v = s_y[i];
        if (v != 0.f) atomicAdd(&y[i], v);
    }
}

// ---- launch ------------------------------------------------------------------
extern "C" void kernel_launch(void* const* d_in, const int* in_sizes, int n_in,
                              void* d_out, int out_size) {
    const float* pos     = (const float*)d_in[0];  // (N,3)  f32
    const float* ks      = (const float*)d_in[1];  // (DEGS,T,T) f32
    const float* v0      = (const float*)d_in[2];  // (T,T) f32
    const int*   mapping = (const int*)d_in[3];    // (2,E) int32
    const int*   types   = (const int*)d_in[4];    // (N,)  int32
    const int*   mbatch  = (const int*)d_in[5];    // (E,)  int32, sorted
    float* y = (float*)d_out;                      // (G,)  f32

    const int N  = in_sizes[0] / 3;
    const int TT = in_sizes[2];           // T*T
    int T = 1;
    while ((T + 1) * (T + 1) <= TT) ++T;  // integer sqrt
    const int degs = in_sizes[1] / TT;
    const long long E = (long long)in_sizes[5];
    const int G = out_size;

    const int* map0 = mapping;
    const int* map1 = mapping + E;
    const long long C = E >> 2;           // 4 edges per chunk

    cudaMemsetAsync(d_out, 0, (size_t)out_size * sizeof(float), 0);

    int prep_blocks = (N + 255) / 256;
    pack_nodes_kernel<<<prep_blocks, 256>>>(pos, types, N);

    int blocks = 148 * 8;
    poly_main_kernel<<<blocks, 256>>>(map0, map1, mbatch, ks, v0, y,
                                      C, E, T, degs, G);
}